// round 8
// baseline (speedup 1.0000x reference)
#include <cuda_runtime.h>
#include <math.h>

// Problem constants (fixed by the reference)
#define TT   256
#define BB   128
#define CC   512
#define HH   512
#define LL   2
#define KDIM 1024          // C+H == 2H
#define NG   2048          // 4H
#define BHN  (BB*HH)       // 65536
#define NCTA 128           // persistent grid (<= 148 SMs -> all co-resident)

// ---------------- scratch (static __device__, no allocations) ----------------
__device__ float d_y0[(size_t)TT*BB*HH];  // layer-0 output (64 MB)
__device__ float d_Z [(size_t)TT*BB*NG];  // precomputed x-part of outer gates (+bias), 256 MB
__device__ float d_h[BHN];                // outer hidden
__device__ float d_c[BHN];                // outer cell state
__device__ float d_hi[2][BHN];            // inner hidden (ping-pong)
__device__ float d_ci[BHN];               // inner cell state
__device__ float d_cell[BHN];             // outer candidate cell (input to inner GEMM)
__device__ float d_sigo[BHN];             // sigmoid(outer o-gate)
__device__ unsigned int g_bar;            // grid barrier counter (reset per launch by reset node)

__device__ __forceinline__ float sigmf(float x) { return 1.0f / (1.0f + expf(-x)); }

__global__ void reset_bar_kernel() { g_bar = 0u; }

// Software grid barrier: all NCTA CTAs co-resident; monotonic counter, epoch
// tracked identically by every thread. Classic fence+atomic+spin pattern.
__device__ __forceinline__ void gsync(unsigned int& epoch)
{
    ++epoch;
    __syncthreads();
    if (threadIdx.x == 0) {
        __threadfence();
        atomicAdd(&g_bar, 1u);
        const unsigned int target = epoch * (unsigned int)NCTA;
        while (*(volatile unsigned int*)&g_bar < target) { }
        __threadfence();
    }
    __syncthreads();
}

// ---------------- GEMM tile (known-good math from round 3/7 kernel) ----------
// out[b, n] += sum_k A[b,k] * W[n,k], A row stride 512, W row stride KDIM.
// Tile: BM=64 rows (m0), BN=32 cols = 4 gates x 8 j-indices (weight rows g*512+j0+jj).
// 256 threads, thread tile 4x2. KT = number of 32-wide K tiles (16 or 32).
// A is given as up to two 512-wide halves (A0 for k<512, A1 for k>=512).
template<int KT>
__device__ __forceinline__ void gemm_tile(const float* __restrict__ A0,
                                          const float* __restrict__ A1,
                                          const float* __restrict__ W,  // col-offset folded in
                                          float* As, float* Bs,
                                          int m0, int j0, int lrow, int lk4,
                                          int tm, int tn, float acc[4][2])
{
    const int wrow = ((lrow >> 3) * HH) + j0 + (lrow & 7);
    const float4* Wp = reinterpret_cast<const float4*>(W + (size_t)wrow * KDIM) + lk4;

    float4 a0, a1, wv;
    a0 = *reinterpret_cast<const float4*>(A0 + (size_t)(m0      + lrow) * 512 + lk4 * 4);
    a1 = *reinterpret_cast<const float4*>(A0 + (size_t)(m0 + 32 + lrow) * 512 + lk4 * 4);
    wv = Wp[0];

    #pragma unroll 1
    for (int kt = 0; kt < KT; ++kt) {
        __syncthreads();             // previous tile's readers (or previous epilogue) done
        {
            const int kb = lk4 * 4;
            As[(kb + 0) * 68 + lrow]      = a0.x;
            As[(kb + 1) * 68 + lrow]      = a0.y;
            As[(kb + 2) * 68 + lrow]      = a0.z;
            As[(kb + 3) * 68 + lrow]      = a0.w;
            As[(kb + 0) * 68 + 32 + lrow] = a1.x;
            As[(kb + 1) * 68 + 32 + lrow] = a1.y;
            As[(kb + 2) * 68 + 32 + lrow] = a1.z;
            As[(kb + 3) * 68 + 32 + lrow] = a1.w;
            Bs[(kb + 0) * 34 + lrow] = wv.x;
            Bs[(kb + 1) * 34 + lrow] = wv.y;
            Bs[(kb + 2) * 34 + lrow] = wv.z;
            Bs[(kb + 3) * 34 + lrow] = wv.w;
        }
        __syncthreads();

        // prefetch next tile (redundant reload of last tile on final iter — harmless)
        {
            const int ktn = (kt < KT - 1) ? (kt + 1) : kt;
            const int k0  = ktn * 32;
            const float* Ap = (k0 < 512) ? A0 : A1;
            const int kl    = k0 & 511;
            a0 = *reinterpret_cast<const float4*>(Ap + (size_t)(m0      + lrow) * 512 + kl + lk4 * 4);
            a1 = *reinterpret_cast<const float4*>(Ap + (size_t)(m0 + 32 + lrow) * 512 + kl + lk4 * 4);
            wv = Wp[(size_t)ktn * 8];
        }

        #pragma unroll
        for (int kk = 0; kk < 32; ++kk) {
            float4 av = *reinterpret_cast<const float4*>(&As[kk * 68 + tm * 4]);
            float2 bv = *reinterpret_cast<const float2*>(&Bs[kk * 34 + tn * 2]);
            acc[0][0] += av.x * bv.x;  acc[0][1] += av.x * bv.y;
            acc[1][0] += av.y * bv.x;  acc[1][1] += av.y * bv.y;
            acc[2][0] += av.z * bv.x;  acc[2][1] += av.z * bv.y;
            acc[3][0] += av.w * bv.x;  acc[3][1] += av.w * bv.y;
        }
    }
}

// ---------------- persistent kernel: whole network in one launch ----------------
__global__ __launch_bounds__(256, 1)
void nested_lstm_persistent(const float* __restrict__ x,
                            const float* __restrict__ h0,
                            const float* __restrict__ Wg,
                            const float* __restrict__ bg,
                            const float* __restrict__ Wi,
                            const float* __restrict__ bi,
                            float* __restrict__ out)
{
    __shared__ float smem[32 * 68 + 32 * 34];
    float* As = smem;
    float* Bs = smem + 32 * 68;
    float* sG = smem;                        // epilogue reuse: [64][33] fits

    const int tid  = threadIdx.x;
    const int cta  = blockIdx.x;             // 0..127
    const int m0   = (cta & 1) * 64;
    const int j0   = (cta >> 1) * 8;
    const int tm   = tid >> 4;
    const int tn   = tid & 15;
    const int lrow = tid >> 3;
    const int lk4  = tid & 7;
    const int gtid = cta * 256 + tid;

    unsigned int epoch = 0;

    for (int l = 0; l < LL; ++l) {
        // ---- init recurrent state for this layer ----
        {
            const float* p = h0 + (size_t)l * 4 * BHN;
            for (int i = gtid; i < BHN; i += NCTA * 256) {
                d_h[i]     = p[i];
                d_c[i]     = p[BHN + i];
                d_hi[0][i] = p[2 * BHN + i];
                d_ci[i]    = p[3 * BHN + i];
            }
        }
        const float* Wgl = Wg + (size_t)l * NG * KDIM;
        const float* bgl = bg + (size_t)l * NG;
        const float* Wil = Wi + (size_t)l * NG * KDIM;
        const float* bil = bi + (size_t)l * NG;
        const float* Ain = (l == 0) ? x : d_y0;     // both row-stride 512
        float*       yo  = (l == 0) ? d_y0 : out;

        gsync(epoch);   // state init visible; prev layer's d_y0 complete

        // ---- Phase A (parallel over t): Z[t] = Ain_t @ Wgx^T + bg ----
        // Each CTA keeps its fixed (m0, j0) weight tile hot across all t.
        for (int t = 0; t < TT; ++t) {
            float acc[4][2] = {};
            gemm_tile<16>(Ain + (size_t)t * BB * 512, nullptr, Wgl,
                          As, Bs, m0, j0, lrow, lk4, tm, tn, acc);
            float* Zt = d_Z + (size_t)t * BB * NG;
            #pragma unroll
            for (int i = 0; i < 4; ++i)
                #pragma unroll
                for (int jj = 0; jj < 2; ++jj) {
                    const int c  = tn * 2 + jj;
                    const int wr = ((c >> 3) * HH) + j0 + (c & 7);
                    Zt[(size_t)(m0 + tm * 4 + i) * NG + wr] = acc[i][jj] + bgl[wr];
                }
        }
        gsync(epoch);

        // ---- Sequential recurrence ----
        const float* Whl = Wgl + 512;   // h-columns of Wg rows
        for (int t = 0; t < TT; ++t) {
            const int par = t & 1;

            // outer: gates = h @ Wgh^T + Z[t]
            {
                float acc[4][2] = {};
                gemm_tile<16>(d_h, nullptr, Whl, As, Bs, m0, j0, lrow, lk4, tm, tn, acc);
                const float* Zt = d_Z + (size_t)t * BB * NG;
                __syncthreads();
                #pragma unroll
                for (int i = 0; i < 4; ++i)
                    #pragma unroll
                    for (int jj = 0; jj < 2; ++jj) {
                        const int c  = tn * 2 + jj;
                        const int wr = ((c >> 3) * HH) + j0 + (c & 7);
                        sG[(tm * 4 + i) * 33 + c] =
                            acc[i][jj] + Zt[(size_t)(m0 + tm * 4 + i) * NG + wr];
                    }
                __syncthreads();
                for (int e = tid; e < 64 * 8; e += 256) {
                    const int row = e & 63;
                    const int jj  = e >> 6;
                    const int idx = (m0 + row) * HH + j0 + jj;
                    const float gi = sG[row * 33 + jj];
                    const float gf = sG[row * 33 +  8 + jj];
                    const float go = sG[row * 33 + 16 + jj];
                    const float gc = sG[row * 33 + 24 + jj];
                    d_cell[idx] = sigmf(gf) * d_c[idx] + sigmf(gi) * tanhf(gc);
                    d_sigo[idx] = sigmf(go);
                }
            }
            gsync(epoch);   // d_cell/d_sigo complete before inner GEMM reads them

            // inner: gates2 = [cell, hi] @ Wi^T + bi
            {
                float acc[4][2] = {};
                gemm_tile<32>(d_cell, d_hi[par], Wil, As, Bs, m0, j0, lrow, lk4, tm, tn, acc);
                __syncthreads();
                #pragma unroll
                for (int i = 0; i < 4; ++i)
                    #pragma unroll
                    for (int jj = 0; jj < 2; ++jj) {
                        const int c  = tn * 2 + jj;
                        const int wr = ((c >> 3) * HH) + j0 + (c & 7);
                        sG[(tm * 4 + i) * 33 + c] = acc[i][jj] + bil[wr];
                    }
                __syncthreads();
                for (int e = tid; e < 64 * 8; e += 256) {
                    const int row = e & 63;
                    const int jj  = e >> 6;
                    const int idx = (m0 + row) * HH + j0 + jj;
                    const float gi = sG[row * 33 + jj];
                    const float gf = sG[row * 33 +  8 + jj];
                    const float go = sG[row * 33 + 16 + jj];
                    const float gc = sG[row * 33 + 24 + jj];
                    const float cin = sigmf(gf) * d_ci[idx] + sigmf(gi) * tanhf(gc);
                    const float hin = sigmf(go) * tanhf(cin);
                    const float hn  = d_sigo[idx] * tanhf(hin);
                    d_ci[idx]          = cin;
                    d_hi[par ^ 1][idx] = hin;
                    d_c[idx]           = hin;   // carry: c <- hi_n
                    d_h[idx]           = hn;
                    yo[(size_t)t * BB * HH + idx] = hn;
                }
            }
            gsync(epoch);   // h/c/hi/ci/y complete before next step's outer GEMM
        }
    }
}

extern "C" void kernel_launch(void* const* d_in, const int* in_sizes, int n_in,
                              void* d_out, int out_size)
{
    const float* x  = (const float*)d_in[0];   // (T,B,C)
    const float* h0 = (const float*)d_in[1];   // (L,4,B,H)
    const float* Wg = (const float*)d_in[2];   // (L,4H,C+H)
    const float* bg = (const float*)d_in[3];   // (L,4H)
    const float* Wi = (const float*)d_in[4];   // (L,4H,2H)
    const float* bi = (const float*)d_in[5];   // (L,4H)
    float* out = (float*)d_out;                // (T,B,H) f32

    reset_bar_kernel<<<1, 1>>>();
    nested_lstm_persistent<<<NCTA, 256>>>(x, h0, Wg, bg, Wi, bi, out);
}

// round 9
// speedup vs baseline: 1.0003x; 1.0003x over previous
#include <cuda_runtime.h>
#include <math.h>

// Problem constants (fixed by the reference)
#define TT   256
#define BB   128
#define CC   512
#define HH   512
#define LL   2
#define KDIM 1024          // C+H == 2H
#define NG   2048          // 4H
#define BHN  (BB*HH)       // 65536
#define NCTA 128           // persistent grid (<= 148 SMs -> all co-resident)

// ---------------- scratch (static __device__, no allocations) ----------------
__device__ float d_y0[(size_t)TT*BB*HH];  // layer-0 output (64 MB)
__device__ float d_Z [(size_t)TT*BB*NG];  // precomputed x-part of outer gates (+bias), 256 MB
__device__ float d_h[BHN];                // outer hidden
__device__ float d_c[BHN];                // outer cell state
__device__ float d_hi[2][BHN];            // inner hidden (ping-pong)
__device__ float d_ci[BHN];               // inner cell state
__device__ float d_cell[BHN];             // outer candidate cell (input to inner GEMM)
__device__ float d_sigo[BHN];             // sigmoid(outer o-gate)
__device__ unsigned int g_bar;            // grid barrier counter (reset per launch by reset node)

__device__ __forceinline__ float sigmf(float x) { return 1.0f / (1.0f + expf(-x)); }

__global__ void reset_bar_kernel() { g_bar = 0u; }

// Software grid barrier: all NCTA CTAs co-resident; monotonic counter, epoch
// tracked identically by every thread. Classic fence+atomic+spin pattern.
__device__ __forceinline__ void gsync(unsigned int& epoch)
{
    ++epoch;
    __syncthreads();
    if (threadIdx.x == 0) {
        __threadfence();
        atomicAdd(&g_bar, 1u);
        const unsigned int target = epoch * (unsigned int)NCTA;
        while (*(volatile unsigned int*)&g_bar < target) { }
        __threadfence();
    }
    __syncthreads();
}

// ---------------- GEMM tile (known-good math from round 3/7 kernel) ----------
// out[b, n] += sum_k A[b,k] * W[n,k], A row stride 512, W row stride KDIM.
// Tile: BM=64 rows (m0), BN=32 cols = 4 gates x 8 j-indices (weight rows g*512+j0+jj).
// 256 threads, thread tile 4x2. KT = number of 32-wide K tiles (16 or 32).
// A is given as up to two 512-wide halves (A0 for k<512, A1 for k>=512).
template<int KT>
__device__ __forceinline__ void gemm_tile(const float* __restrict__ A0,
                                          const float* __restrict__ A1,
                                          const float* __restrict__ W,  // col-offset folded in
                                          float* As, float* Bs,
                                          int m0, int j0, int lrow, int lk4,
                                          int tm, int tn, float acc[4][2])
{
    const int wrow = ((lrow >> 3) * HH) + j0 + (lrow & 7);
    const float4* Wp = reinterpret_cast<const float4*>(W + (size_t)wrow * KDIM) + lk4;

    float4 a0, a1, wv;
    a0 = *reinterpret_cast<const float4*>(A0 + (size_t)(m0      + lrow) * 512 + lk4 * 4);
    a1 = *reinterpret_cast<const float4*>(A0 + (size_t)(m0 + 32 + lrow) * 512 + lk4 * 4);
    wv = Wp[0];

    #pragma unroll 1
    for (int kt = 0; kt < KT; ++kt) {
        __syncthreads();             // previous tile's readers (or previous epilogue) done
        {
            const int kb = lk4 * 4;
            As[(kb + 0) * 68 + lrow]      = a0.x;
            As[(kb + 1) * 68 + lrow]      = a0.y;
            As[(kb + 2) * 68 + lrow]      = a0.z;
            As[(kb + 3) * 68 + lrow]      = a0.w;
            As[(kb + 0) * 68 + 32 + lrow] = a1.x;
            As[(kb + 1) * 68 + 32 + lrow] = a1.y;
            As[(kb + 2) * 68 + 32 + lrow] = a1.z;
            As[(kb + 3) * 68 + 32 + lrow] = a1.w;
            Bs[(kb + 0) * 34 + lrow] = wv.x;
            Bs[(kb + 1) * 34 + lrow] = wv.y;
            Bs[(kb + 2) * 34 + lrow] = wv.z;
            Bs[(kb + 3) * 34 + lrow] = wv.w;
        }
        __syncthreads();

        // prefetch next tile (redundant reload of last tile on final iter — harmless)
        {
            const int ktn = (kt < KT - 1) ? (kt + 1) : kt;
            const int k0  = ktn * 32;
            const float* Ap = (k0 < 512) ? A0 : A1;
            const int kl    = k0 & 511;
            a0 = *reinterpret_cast<const float4*>(Ap + (size_t)(m0      + lrow) * 512 + kl + lk4 * 4);
            a1 = *reinterpret_cast<const float4*>(Ap + (size_t)(m0 + 32 + lrow) * 512 + kl + lk4 * 4);
            wv = Wp[(size_t)ktn * 8];
        }

        #pragma unroll
        for (int kk = 0; kk < 32; ++kk) {
            float4 av = *reinterpret_cast<const float4*>(&As[kk * 68 + tm * 4]);
            float2 bv = *reinterpret_cast<const float2*>(&Bs[kk * 34 + tn * 2]);
            acc[0][0] += av.x * bv.x;  acc[0][1] += av.x * bv.y;
            acc[1][0] += av.y * bv.x;  acc[1][1] += av.y * bv.y;
            acc[2][0] += av.z * bv.x;  acc[2][1] += av.z * bv.y;
            acc[3][0] += av.w * bv.x;  acc[3][1] += av.w * bv.y;
        }
    }
}

// ---------------- persistent kernel: whole network in one launch ----------------
__global__ __launch_bounds__(256, 1)
void nested_lstm_persistent(const float* __restrict__ x,
                            const float* __restrict__ h0,
                            const float* __restrict__ Wg,
                            const float* __restrict__ bg,
                            const float* __restrict__ Wi,
                            const float* __restrict__ bi,
                            float* __restrict__ out)
{
    __shared__ float smem[32 * 68 + 32 * 34];
    float* As = smem;
    float* Bs = smem + 32 * 68;
    float* sG = smem;                        // epilogue reuse: [64][33] fits

    const int tid  = threadIdx.x;
    const int cta  = blockIdx.x;             // 0..127
    const int m0   = (cta & 1) * 64;
    const int j0   = (cta >> 1) * 8;
    const int tm   = tid >> 4;
    const int tn   = tid & 15;
    const int lrow = tid >> 3;
    const int lk4  = tid & 7;
    const int gtid = cta * 256 + tid;

    unsigned int epoch = 0;

    for (int l = 0; l < LL; ++l) {
        // ---- init recurrent state for this layer ----
        {
            const float* p = h0 + (size_t)l * 4 * BHN;
            for (int i = gtid; i < BHN; i += NCTA * 256) {
                d_h[i]     = p[i];
                d_c[i]     = p[BHN + i];
                d_hi[0][i] = p[2 * BHN + i];
                d_ci[i]    = p[3 * BHN + i];
            }
        }
        const float* Wgl = Wg + (size_t)l * NG * KDIM;
        const float* bgl = bg + (size_t)l * NG;
        const float* Wil = Wi + (size_t)l * NG * KDIM;
        const float* bil = bi + (size_t)l * NG;
        const float* Ain = (l == 0) ? x : d_y0;     // both row-stride 512
        float*       yo  = (l == 0) ? d_y0 : out;

        gsync(epoch);   // state init visible; prev layer's d_y0 complete

        // ---- Phase A (parallel over t): Z[t] = Ain_t @ Wgx^T + bg ----
        // Each CTA keeps its fixed (m0, j0) weight tile hot across all t.
        for (int t = 0; t < TT; ++t) {
            float acc[4][2] = {};
            gemm_tile<16>(Ain + (size_t)t * BB * 512, nullptr, Wgl,
                          As, Bs, m0, j0, lrow, lk4, tm, tn, acc);
            float* Zt = d_Z + (size_t)t * BB * NG;
            #pragma unroll
            for (int i = 0; i < 4; ++i)
                #pragma unroll
                for (int jj = 0; jj < 2; ++jj) {
                    const int c  = tn * 2 + jj;
                    const int wr = ((c >> 3) * HH) + j0 + (c & 7);
                    Zt[(size_t)(m0 + tm * 4 + i) * NG + wr] = acc[i][jj] + bgl[wr];
                }
        }
        gsync(epoch);

        // ---- Sequential recurrence ----
        const float* Whl = Wgl + 512;   // h-columns of Wg rows
        for (int t = 0; t < TT; ++t) {
            const int par = t & 1;

            // outer: gates = h @ Wgh^T + Z[t]
            {
                float acc[4][2] = {};
                gemm_tile<16>(d_h, nullptr, Whl, As, Bs, m0, j0, lrow, lk4, tm, tn, acc);
                const float* Zt = d_Z + (size_t)t * BB * NG;
                __syncthreads();
                #pragma unroll
                for (int i = 0; i < 4; ++i)
                    #pragma unroll
                    for (int jj = 0; jj < 2; ++jj) {
                        const int c  = tn * 2 + jj;
                        const int wr = ((c >> 3) * HH) + j0 + (c & 7);
                        sG[(tm * 4 + i) * 33 + c] =
                            acc[i][jj] + Zt[(size_t)(m0 + tm * 4 + i) * NG + wr];
                    }
                __syncthreads();
                for (int e = tid; e < 64 * 8; e += 256) {
                    const int row = e & 63;
                    const int jj  = e >> 6;
                    const int idx = (m0 + row) * HH + j0 + jj;
                    const float gi = sG[row * 33 + jj];
                    const float gf = sG[row * 33 +  8 + jj];
                    const float go = sG[row * 33 + 16 + jj];
                    const float gc = sG[row * 33 + 24 + jj];
                    d_cell[idx] = sigmf(gf) * d_c[idx] + sigmf(gi) * tanhf(gc);
                    d_sigo[idx] = sigmf(go);
                }
            }
            gsync(epoch);   // d_cell/d_sigo complete before inner GEMM reads them

            // inner: gates2 = [cell, hi] @ Wi^T + bi
            {
                float acc[4][2] = {};
                gemm_tile<32>(d_cell, d_hi[par], Wil, As, Bs, m0, j0, lrow, lk4, tm, tn, acc);
                __syncthreads();
                #pragma unroll
                for (int i = 0; i < 4; ++i)
                    #pragma unroll
                    for (int jj = 0; jj < 2; ++jj) {
                        const int c  = tn * 2 + jj;
                        const int wr = ((c >> 3) * HH) + j0 + (c & 7);
                        sG[(tm * 4 + i) * 33 + c] = acc[i][jj] + bil[wr];
                    }
                __syncthreads();
                for (int e = tid; e < 64 * 8; e += 256) {
                    const int row = e & 63;
                    const int jj  = e >> 6;
                    const int idx = (m0 + row) * HH + j0 + jj;
                    const float gi = sG[row * 33 + jj];
                    const float gf = sG[row * 33 +  8 + jj];
                    const float go = sG[row * 33 + 16 + jj];
                    const float gc = sG[row * 33 + 24 + jj];
                    const float cin = sigmf(gf) * d_ci[idx] + sigmf(gi) * tanhf(gc);
                    const float hin = sigmf(go) * tanhf(cin);
                    const float hn  = d_sigo[idx] * tanhf(hin);
                    d_ci[idx]          = cin;
                    d_hi[par ^ 1][idx] = hin;
                    d_c[idx]           = hin;   // carry: c <- hi_n
                    d_h[idx]           = hn;
                    yo[(size_t)t * BB * HH + idx] = hn;
                }
            }
            gsync(epoch);   // h/c/hi/ci/y complete before next step's outer GEMM
        }
    }
}

extern "C" void kernel_launch(void* const* d_in, const int* in_sizes, int n_in,
                              void* d_out, int out_size)
{
    const float* x  = (const float*)d_in[0];   // (T,B,C)
    const float* h0 = (const float*)d_in[1];   // (L,4,B,H)
    const float* Wg = (const float*)d_in[2];   // (L,4H,C+H)
    const float* bg = (const float*)d_in[3];   // (L,4H)
    const float* Wi = (const float*)d_in[4];   // (L,4H,2H)
    const float* bi = (const float*)d_in[5];   // (L,4H)
    float* out = (float*)d_out;                // (T,B,H) f32

    reset_bar_kernel<<<1, 1>>>();
    nested_lstm_persistent<<<NCTA, 256>>>(x, h0, Wg, bg, Wi, bi, out);
}